// round 3
// baseline (speedup 1.0000x reference)
#include <cuda_runtime.h>
#include <cuda_bf16.h>
#include <cstdint>

#define NN   256
#define NE   1024
#define MAXC 64
#define WINF (1<<20)

typedef unsigned long long ull;

// ---------------- resettable state (memset per replay) ----------------
struct Flags {
    int done[NN * 64];   // (neuron, batch-pair) completion flags
    int sched_ready;
};
__device__ Flags g_flags;
__device__ float g_hidden[128 * 200];   // raw FC1 sums (bias/relu applied in FC2)

// ---------------- persistent scratch (rewritten before use) ----------------
__device__ float g_act[(size_t)NN * 128 * 784];   // [n][b][p]
__device__ int   g_fin[NN * MAXC];
__device__ int   g_fcc[NN * MAXC];
__device__ int   g_fdeg[NN];
__device__ int   g_order[NN];
__device__ int   g_ntasks;

#define FMA_F32X2(d, a, b) \
    asm("fma.rn.f32x2 %0, %1, %2, %0;" : "+l"(d) : "l"(a), "l"(b))

// 7-pixel horizontal register tile
__device__ __forceinline__ void conv_accum(const float* __restrict__ im,
                                           const float* __restrict__ wk,
                                           float acc[7]) {
#pragma unroll
    for (int dy = 0; dy < 5; ++dy) {
        const float* rp = im + dy * 33;
        float v[11];
#pragma unroll
        for (int j = 0; j < 11; ++j) v[j] = rp[j];
#pragma unroll
        for (int dx = 0; dx < 5; ++dx) {
            float wv = wk[dy * 5 + dx];
#pragma unroll
            for (int o = 0; o < 7; ++o) acc[o] += wv * v[dx + o];
        }
    }
}

// =====================================================================
// K1: scheduler (block 0) + wave0 + dataflow conv
// =====================================================================
__global__ void __launch_bounds__(224) net_kernel(
    const float* __restrict__ x,
    const int* __restrict__ src, const int* __restrict__ tgt,
    const float* __restrict__ conv_w, const float* __restrict__ conv_b,
    int cmax, int nb)
{
    __shared__ float img[2][2112];       // double-buffered pair of 32x33 images
    __shared__ float wkAll[18 * 25];     // prefetched channel weights
    __shared__ int s_src[NE], s_tgt[NE];
    __shared__ int s_wave[NN], s_need[NN], s_list[NN];
    __shared__ int s_chg, s_cnt;

    const int tid = threadIdx.x;
    const int bid = blockIdx.x;

    for (int i = tid; i < 2112; i += 224) { img[0][i] = 0.f; img[1][i] = 0.f; }

    const int bl   = tid / 112;
    const int tile = tid % 112;
    const int y    = tile >> 2;
    const int x0   = (tile & 3) * 7;
    int ldoff[7];
#pragma unroll
    for (int k = 0; k < 7; ++k) {
        int i  = tid + k * 224;
        int bb = i / 784;
        int p  = i - bb * 784;
        int r  = p / 28;
        ldoff[k] = bb * 1056 + (r + 2) * 33 + (p - r * 28) + 2;
    }
    const int ibase = bl * 1056 + y * 33 + x0;
    const int doff  = y * 28 + x0;
    __syncthreads();

    // ---------------- block 0: schedule only ----------------
    if (bid == 0) {
        for (int i = tid; i < NE; i += 224) { s_src[i] = src[i]; s_tgt[i] = tgt[i]; }
        for (int i = tid; i < NN; i += 224) { s_wave[i] = (i == 0) ? 0 : WINF; s_need[i] = 0; }
        if (tid == 0) { s_chg = 0; s_cnt = 0; }
        __syncthreads();

        for (int pass = 0; pass < 300; ++pass) {
            for (int e = tid; e < NE; e += 224) {
                int ws = s_wave[s_src[e]];
                if (ws + 1 < s_wave[s_tgt[e]]) { atomicMin(&s_wave[s_tgt[e]], ws + 1); s_chg = 1; }
            }
            __syncthreads();
            int c = s_chg; __syncthreads();
            if (tid == 0) s_chg = 0;
            __syncthreads();
            if (!c) break;
        }

        if (tid == 0) s_need[255] = 1;
        __syncthreads();
        for (int pass = 0; pass < 300; ++pass) {
            for (int e = tid; e < NE; e += 224) {
                int s = s_src[e], t = s_tgt[e];
                if (s_need[t] && s_wave[s] < s_wave[t] && !s_need[s]) { s_need[s] = 1; s_chg = 1; }
            }
            __syncthreads();
            int c = s_chg; __syncthreads();
            if (tid == 0) s_chg = 0;
            __syncthreads();
            if (!c) break;
        }

        for (int n = tid; n < NN; n += 224) {
            if (n != 0 && n != 255 && s_need[n]) {
                int r = 0;
                for (int m = 1; m < NN - 1; ++m)
                    if (s_need[m] && (s_wave[m] < s_wave[n] ||
                                      (s_wave[m] == s_wave[n] && m < n))) r++;
                s_list[r] = n;
                atomicAdd(&s_cnt, 1);
            }
        }
        __syncthreads();
        const int total = s_cnt;

        {
            const int wid = tid >> 5, lane = tid & 31;
            for (int ni = wid; ni <= total; ni += 7) {
                int n  = (ni == total) ? 255 : s_list[ni];
                int wn = s_wave[n];
                int cbase = 0, cnt = 0;
                for (int ch = 0; ch < NE; ch += 32) {
                    int e = ch + lane;
                    int te = s_tgt[e], se = s_src[e];
                    unsigned m_all  = __ballot_sync(0xffffffffu, te == n);
                    unsigned m_keep = __ballot_sync(0xffffffffu, te == n && s_wave[se] < wn);
                    if (m_keep & (1u << lane)) {
                        int c   = cbase + __popc(m_all  & ((1u << lane) - 1));
                        int pos = cnt   + __popc(m_keep & ((1u << lane) - 1));
                        if (pos < MAXC) { g_fin[n * MAXC + pos] = se; g_fcc[n * MAXC + pos] = c; }
                    }
                    cbase += __popc(m_all);
                    cnt   += __popc(m_keep);
                }
                if (lane == 0) g_fdeg[n] = cnt < MAXC ? cnt : MAXC;
            }
        }
        for (int i = tid; i < total; i += 224) g_order[i] = s_list[i];
        if (tid == 0) g_ntasks = total * 64;
        __threadfence();
        __syncthreads();
        if (tid == 0) *(volatile int*)&g_flags.sched_ready = 1;
        return;   // block 0 does nothing else
    }

    // ---------------- wave 0 on blocks 1..64 ----------------
    {
        const float bias = conv_b[0];
        for (int t = bid - 1; t < 64; t += nb - 1) {
            const float* sp = x + (size_t)t * 1568;
#pragma unroll
            for (int k = 0; k < 7; ++k) img[0][ldoff[k]] = sp[tid + k * 224];
            if (tid < 25) wkAll[tid] = conv_w[tid];
            __syncthreads();
            float acc[7];
#pragma unroll
            for (int o = 0; o < 7; ++o) acc[o] = bias;
            conv_accum(&img[0][ibase], wkAll, acc);
            float* dst = g_act + (size_t)(t * 2 + bl) * 784 + doff;
#pragma unroll
            for (int o = 0; o < 7; ++o) dst[o] = fmaxf(acc[o], 0.f);
            __threadfence();
            __syncthreads();
            if (tid == 0) *(volatile int*)&g_flags.done[t] = 1;
        }
    }

    // ---------------- wait schedule ----------------
    if (tid == 0) {
        volatile int* f = &g_flags.sched_ready;
        while (!*f) __nanosleep(64);
    }
    __syncthreads();
    __threadfence();

    // ---------------- dataflow conv tasks ----------------
    const int ntasks = g_ntasks;
    for (int t = bid - 1; t < ntasks; t += nb - 1) {
        const int ni = t >> 6;
        const int pb = t & 63;
        const int n  = g_order[ni];
        const int C  = g_fdeg[n];
        const float* wbase = conv_w + (size_t)n * cmax * 25;

        // prefetch weights (flag-independent)
        const int CW = C < 16 ? C : 16;
        for (int i = tid; i < CW * 25; i += 224) {
            int c = i / 25;
            wkAll[i] = wbase[g_fcc[n * MAXC + c] * 25 + (i - c * 25)];
        }
        // wait for inputs
        for (int k = tid; k < C; k += 224) {
            volatile int* f = &g_flags.done[g_fin[n * MAXC + k] * 64 + pb];
            while (!*f) __nanosleep(32);
        }
        __syncthreads();
        __threadfence();

        float acc[7];
        const float bias = conv_b[n];
#pragma unroll
        for (int o = 0; o < 7; ++o) acc[o] = bias;

        // stage channel 0
        {
            const float* sp = g_act + ((size_t)g_fin[n * MAXC] * 128 + pb * 2) * 784;
#pragma unroll
            for (int k = 0; k < 7; ++k) img[0][ldoff[k]] = sp[tid + k * 224];
        }
        __syncthreads();

        for (int c = 0; c < C; ++c) {
            const int buf = c & 1;
            if (c + 1 < C) {   // prefetch next channel into other buffer
                const float* sp = g_act + ((size_t)g_fin[n * MAXC + c + 1] * 128 + pb * 2) * 784;
#pragma unroll
                for (int k = 0; k < 7; ++k) img[buf ^ 1][ldoff[k]] = sp[tid + k * 224];
                if (c + 1 >= 16 && tid < 25)   // overflow weight slot (ping-pong 16/17)
                    wkAll[(16 + ((c + 1) & 1)) * 25 + tid] =
                        wbase[g_fcc[n * MAXC + c + 1] * 25 + tid];
            }
            const float* wp = (c < 16) ? &wkAll[c * 25] : &wkAll[(16 + (c & 1)) * 25];
            conv_accum(&img[buf][ibase], wp, acc);
            __syncthreads();
        }
        float* dst = g_act + ((size_t)n * 128 + pb * 2 + bl) * 784 + doff;
#pragma unroll
        for (int o = 0; o < 7; ++o) dst[o] = fmaxf(acc[o], 0.f);
        __threadfence();
        __syncthreads();
        if (tid == 0) *(volatile int*)&g_flags.done[n * 64 + pb] = 1;
    }
}

// =====================================================================
// K2: FC1 GEMM, packed f32x2. Block tile 64h x 128b, grid (4 ht, 7 ps, 8 cs).
// Partial sums atomicAdd'ed into g_hidden (raw, bias/relu in FC2).
// =====================================================================
__global__ void __launch_bounds__(256) fc1_kernel(const float* __restrict__ fc1_w, int fcK)
{
    __shared__ __align__(16) float  s_w[16][68];    // natural h pairs
    __shared__ __align__(16) float2 s_a[16][130];   // lane-duplicated acts

    const int tid = threadIdx.x;
    const int h0  = blockIdx.x * 64;
    const int ps  = blockIdx.y;
    const int cs  = blockIdx.z;
    const int validh = (200 - h0) < 64 ? (200 - h0) : 64;
    const int fdeg = g_fdeg[255];
    if (cs >= fdeg) return;   // includes fdeg==0 (hidden stays zero)

    const int hg = tid >> 5;          // h = h0 + hg*8 + 0..7
    const int bg = tid & 31;          // b = bg*4 + 0..3

    ull acc[4][4];
#pragma unroll
    for (int i = 0; i < 4; ++i)
#pragma unroll
        for (int j = 0; j < 4; ++j) acc[i][j] = 0ull;

    const int sb = tid >> 2;            // staging row (b or h)
    const int sk = (tid & 3) * 4;       // staging k base

    for (int c = cs; c < fdeg; c += 8) {
        const int in = g_fin[255 * MAXC + c];
        const int cc = g_fcc[255 * MAXC + c];
        const float* abase = g_act + (size_t)in * 128 * 784;
        const float* wbase = fc1_w + (size_t)cc * 784;

        for (int pp = ps * 112; pp < ps * 112 + 112; pp += 16) {
            // stage acts: 128 b x 16 k (dup-packed)
#pragma unroll
            for (int u = 0; u < 2; ++u) {
                int b = sb + u * 64;
                float4 v = *(const float4*)(abase + b * 784 + pp + sk);
                s_a[sk + 0][b] = make_float2(v.x, v.x);
                s_a[sk + 1][b] = make_float2(v.y, v.y);
                s_a[sk + 2][b] = make_float2(v.z, v.z);
                s_a[sk + 3][b] = make_float2(v.w, v.w);
            }
            // stage weights: 64 h x 16 k
            {
                float4 v = (sb < validh)
                    ? *(const float4*)(wbase + (size_t)(h0 + sb) * fcK + pp + sk)
                    : make_float4(0.f, 0.f, 0.f, 0.f);
                s_w[sk + 0][sb] = v.x;
                s_w[sk + 1][sb] = v.y;
                s_w[sk + 2][sb] = v.z;
                s_w[sk + 3][sb] = v.w;
            }
            __syncthreads();
#pragma unroll
            for (int k = 0; k < 16; ++k) {
                ulonglong2 wv0 = *(const ulonglong2*)&s_w[k][hg * 8];
                ulonglong2 wv1 = *(const ulonglong2*)&s_w[k][hg * 8 + 4];
                ulonglong2 av0 = *(const ulonglong2*)&s_a[k][bg * 4];
                ulonglong2 av1 = *(const ulonglong2*)&s_a[k][bg * 4 + 2];
                FMA_F32X2(acc[0][0], wv0.x, av0.x); FMA_F32X2(acc[0][1], wv0.x, av0.y);
                FMA_F32X2(acc[0][2], wv0.x, av1.x); FMA_F32X2(acc[0][3], wv0.x, av1.y);
                FMA_F32X2(acc[1][0], wv0.y, av0.x); FMA_F32X2(acc[1][1], wv0.y, av0.y);
                FMA_F32X2(acc[1][2], wv0.y, av1.x); FMA_F32X2(acc[1][3], wv0.y, av1.y);
                FMA_F32X2(acc[2][0], wv1.x, av0.x); FMA_F32X2(acc[2][1], wv1.x, av0.y);
                FMA_F32X2(acc[2][2], wv1.x, av1.x); FMA_F32X2(acc[2][3], wv1.x, av1.y);
                FMA_F32X2(acc[3][0], wv1.y, av0.x); FMA_F32X2(acc[3][1], wv1.y, av0.y);
                FMA_F32X2(acc[3][2], wv1.y, av1.x); FMA_F32X2(acc[3][3], wv1.y, av1.y);
            }
            __syncthreads();
        }
    }

    if (hg * 8 < validh) {
#pragma unroll
        for (int hp = 0; hp < 4; ++hp)
#pragma unroll
            for (int j = 0; j < 4; ++j) {
                union { ull u; float2 f; } cv; cv.u = acc[hp][j];
                const int h = h0 + hg * 8 + hp * 2;
                const int b = bg * 4 + j;
                atomicAdd(&g_hidden[b * 200 + h],     cv.f.x);
                atomicAdd(&g_hidden[b * 200 + h + 1], cv.f.y);
            }
    }
}

// =====================================================================
// K3: FC2 + log_softmax (bias + relu on raw hidden folded in)
// =====================================================================
__global__ void __launch_bounds__(256) fc2_kernel(
    const float* __restrict__ fc1_b,
    const float* __restrict__ fc2_w, const float* __restrict__ fc2_b,
    float* __restrict__ out)
{
    const int wid  = threadIdx.x >> 5;
    const int lane = threadIdx.x & 31;
    const int b    = blockIdx.x * 8 + wid;

    float acc = 0.f;
    if (lane < 10) {
        acc = fc2_b[lane];
        const float* wp = fc2_w + lane * 200;
        const float* hp = g_hidden + b * 200;
        for (int h = 0; h < 200; ++h)
            acc += fmaxf(hp[h] + fc1_b[h], 0.f) * wp[h];
    }
    float m = (lane < 10) ? acc : -1e30f;
#pragma unroll
    for (int off = 16; off; off >>= 1) m = fmaxf(m, __shfl_xor_sync(0xffffffffu, m, off));
    float e = (lane < 10) ? expf(acc - m) : 0.f;
    float s = e;
#pragma unroll
    for (int off = 16; off; off >>= 1) s += __shfl_xor_sync(0xffffffffu, s, off);
    const float lse = m + logf(s);
    if (lane < 10) out[b * 10 + lane] = acc - lse;
}

// ---------------- launch ----------------
extern "C" void kernel_launch(void* const* d_in, const int* in_sizes, int n_in,
                              void* d_out, int out_size) {
    const float* x      = (const float*)d_in[0];
    const int*   src    = (const int*)  d_in[1];
    const int*   tgt    = (const int*)  d_in[2];
    const float* conv_w = (const float*)d_in[3];
    const float* conv_b = (const float*)d_in[4];
    const float* fc1_w  = (const float*)d_in[5];
    const float* fc1_b  = (const float*)d_in[6];
    const float* fc2_w  = (const float*)d_in[7];
    const float* fc2_b  = (const float*)d_in[8];

    const int cmax = in_sizes[3] / (NN * 25);
    const int fcK  = in_sizes[5] / 200;

    void* flagsPtr = nullptr; void* hidPtr = nullptr;
    cudaGetSymbolAddress(&flagsPtr, g_flags);
    cudaGetSymbolAddress(&hidPtr, g_hidden);
    cudaMemsetAsync(flagsPtr, 0, sizeof(Flags), 0);
    cudaMemsetAsync(hidPtr, 0, 128 * 200 * sizeof(float), 0);

    int dev = 0, sms = 0, occ = 0;
    cudaGetDevice(&dev);
    cudaDeviceGetAttribute(&sms, cudaDevAttrMultiProcessorCount, dev);
    cudaOccupancyMaxActiveBlocksPerMultiprocessor(&occ, net_kernel, 224, 0);
    int nb = sms * occ;
    if (nb < 66) nb = 66;

    net_kernel<<<nb, 224>>>(x, src, tgt, conv_w, conv_b, cmax, nb);
    fc1_kernel<<<dim3(4, 7, 8), 256>>>(fc1_w, fcK);
    fc2_kernel<<<16, 256>>>(fc1_b, fc2_w, fc2_b, (float*)d_out);
}

// round 4
// speedup vs baseline: 1.2063x; 1.2063x over previous
#include <cuda_runtime.h>
#include <cuda_bf16.h>
#include <cstdint>

#define NN   256
#define NE   1024
#define MAXC 64
#define WINF (1<<20)
#define KS   16        // FC1 K-split count

typedef unsigned long long ull;
union F2U { float2 f; ull u; };

// ---------------- resettable state (ONE memset per replay) ----------------
struct __align__(16) Flags {
    float hidden[128 * 200];   // FC1 atomic accumulators (needs zero)
    int   done[NN * 64];       // (neuron, batch-pair) completion flags
    int   hcnt[2];             // FC1 tile counters per 64-batch half
    int   sched_ready;
};
__device__ Flags g_flags;

// ---------------- persistent scratch (rewritten before use) ----------------
__device__ float g_act[(size_t)NN * 128 * 784];   // [n][b][p]
__device__ int   g_fin[NN * MAXC];
__device__ int   g_fcc[NN * MAXC];
__device__ int   g_fdeg[NN];
__device__ int   g_order[NN];
__device__ int   g_ntasks;

#define FMA2(d, a, b) \
    asm("fma.rn.f32x2 %0, %1, %2, %0;" : "+l"(d) : "l"(a), "l"(b))

// ---------------- shared memory union ----------------
struct SchedSM { int src[NE], tgt[NE], wave[NN], need[NN], list[NN]; int chg, cnt; };
struct ConvSM  { float img[2][2112];  ull wk2[18 * 25]; };   // 32x33x2 interleaved, dbl-buf
struct FCSM    { float w[16][74]; float2 a[16][66]; };
union  SMU { SchedSM sch; ConvSM cv; FCSM fc; ull _al; };

// stage one channel (2 batches interleaved) into img buffer
__device__ __forceinline__ void stage_img(float* dst, const float* sp, int tid) {
#pragma unroll
    for (int k = 0; k < 4; ++k) {
        int q = tid + k * 128;
        if (q < 392) {
            int bb = (q >= 196);
            int f4 = q - bb * 196;
            float4 v = __ldg((const float4*)(sp + bb * 784) + f4);
            int row  = f4 / 7;
            int col4 = f4 - row * 7;
            float* d = dst + (row + 2) * 66 + (col4 * 4 + 2) * 2 + bb;
            d[0] = v.x; d[2] = v.y; d[4] = v.z; d[6] = v.w;
        }
    }
}

// 7px x 2batch packed conv: 80 LDS.64 + 175 FFMA2 per channel
__device__ __forceinline__ void conv_acc2(const ull* imb, const ull* w2, ull acc[7]) {
#pragma unroll
    for (int dy = 0; dy < 5; ++dy) {
        const ull* rp = imb + dy * 33;
        ull v[11];
#pragma unroll
        for (int j = 0; j < 11; ++j) v[j] = rp[j];
#pragma unroll
        for (int dx = 0; dx < 5; ++dx) {
            ull wv = w2[dy * 5 + dx];
#pragma unroll
            for (int o = 0; o < 7; ++o) FMA2(acc[o], wv, v[dx + o]);
        }
    }
}

// =====================================================================
// single persistent kernel: sched (block 0) + conv dataflow + FC1 + FC2
// =====================================================================
__global__ void __launch_bounds__(128) net_kernel(
    const float* __restrict__ x,
    const int* __restrict__ src, const int* __restrict__ tgt,
    const float* __restrict__ conv_w, const float* __restrict__ conv_b,
    const float* __restrict__ fc1_w,  const float* __restrict__ fc1_b,
    const float* __restrict__ fc2_w,  const float* __restrict__ fc2_b,
    float* __restrict__ out, int cmax, int fcK, int nb)
{
    __shared__ SMU sm;
    const int tid = threadIdx.x;
    const int bid = blockIdx.x;

    // ================= block 0: scheduler only =================
    if (bid == 0) {
        for (int i = tid; i < NE; i += 128) { sm.sch.src[i] = src[i]; sm.sch.tgt[i] = tgt[i]; }
        for (int i = tid; i < NN; i += 128) { sm.sch.wave[i] = (i == 0) ? 0 : WINF; sm.sch.need[i] = 0; }
        if (tid == 0) { sm.sch.chg = 0; sm.sch.cnt = 0; }
        __syncthreads();

        for (int pass = 0; pass < 300; ++pass) {
            for (int e = tid; e < NE; e += 128) {
                int ws = sm.sch.wave[sm.sch.src[e]];
                if (ws + 1 < sm.sch.wave[sm.sch.tgt[e]]) {
                    atomicMin(&sm.sch.wave[sm.sch.tgt[e]], ws + 1); sm.sch.chg = 1;
                }
            }
            __syncthreads();
            int c = sm.sch.chg; __syncthreads();
            if (tid == 0) sm.sch.chg = 0;
            __syncthreads();
            if (!c) break;
        }

        if (tid == 0) sm.sch.need[255] = 1;
        __syncthreads();
        for (int pass = 0; pass < 300; ++pass) {
            for (int e = tid; e < NE; e += 128) {
                int s = sm.sch.src[e], t = sm.sch.tgt[e];
                if (sm.sch.need[t] && sm.sch.wave[s] < sm.sch.wave[t] && !sm.sch.need[s]) {
                    sm.sch.need[s] = 1; sm.sch.chg = 1;
                }
            }
            __syncthreads();
            int c = sm.sch.chg; __syncthreads();
            if (tid == 0) sm.sch.chg = 0;
            __syncthreads();
            if (!c) break;
        }

        for (int n = tid; n < NN; n += 128) {
            if (n != 0 && n != 255 && sm.sch.need[n]) {
                int r = 0;
                for (int m = 1; m < NN - 1; ++m)
                    if (sm.sch.need[m] && (sm.sch.wave[m] < sm.sch.wave[n] ||
                        (sm.sch.wave[m] == sm.sch.wave[n] && m < n))) r++;
                sm.sch.list[r] = n;
                atomicAdd(&sm.sch.cnt, 1);
            }
        }
        __syncthreads();
        const int total = sm.sch.cnt;

        {   // filtered in-lists via warp ballots
            const int w4 = tid >> 5, lane = tid & 31;
            for (int ni = w4; ni <= total; ni += 4) {
                int n  = (ni == total) ? 255 : sm.sch.list[ni];
                int wn = sm.sch.wave[n];
                int cbase = 0, cnt = 0;
                for (int ch = 0; ch < NE; ch += 32) {
                    int e = ch + lane;
                    int te = sm.sch.tgt[e], se = sm.sch.src[e];
                    unsigned m_all  = __ballot_sync(0xffffffffu, te == n);
                    unsigned m_keep = __ballot_sync(0xffffffffu, te == n && sm.sch.wave[se] < wn);
                    if (m_keep & (1u << lane)) {
                        int c   = cbase + __popc(m_all  & ((1u << lane) - 1));
                        int pos = cnt   + __popc(m_keep & ((1u << lane) - 1));
                        if (pos < MAXC) { g_fin[n * MAXC + pos] = se; g_fcc[n * MAXC + pos] = c; }
                    }
                    cbase += __popc(m_all);
                    cnt   += __popc(m_keep);
                }
                if (lane == 0) g_fdeg[n] = cnt < MAXC ? cnt : MAXC;
            }
        }
        for (int i = tid; i < total; i += 128) g_order[i] = sm.sch.list[i];
        if (tid == 0) g_ntasks = total * 64;
        __threadfence();
        __syncthreads();
        if (tid == 0) *(volatile int*)&g_flags.sched_ready = 1;
        return;
    }

    // ================= worker blocks =================
    for (int i = tid; i < 2 * 2112; i += 128) ((float*)sm.cv.img)[i] = 0.f;
    const int yy  = tid >> 2;          // valid when tid<112
    const int xx0 = (tid & 3) * 7;
    __syncthreads();

    // ---- wave 0: neuron 0 from x ----
    {
        if (tid < 25) { F2U u; float w = conv_w[tid]; u.f = make_float2(w, w); sm.cv.wk2[tid] = u.u; }
        const float bias = conv_b[0];
        for (int t = bid - 1; t < 64; t += nb - 1) {
            stage_img(sm.cv.img[0], x + (size_t)t * 1568, tid);
            __syncthreads();
            if (tid < 112) {
                ull acc[7];
                F2U b2; b2.f = make_float2(bias, bias);
#pragma unroll
                for (int o = 0; o < 7; ++o) acc[o] = b2.u;
                conv_acc2((const ull*)sm.cv.img[0] + yy * 33 + xx0, sm.cv.wk2, acc);
                float* d0 = g_act + (size_t)(t * 2) * 784 + yy * 28 + xx0;
#pragma unroll
                for (int o = 0; o < 7; ++o) {
                    F2U u; u.u = acc[o];
                    d0[o]       = fmaxf(u.f.x, 0.f);
                    d0[784 + o] = fmaxf(u.f.y, 0.f);
                }
            }
            __threadfence();
            __syncthreads();
            if (tid == 0) *(volatile int*)&g_flags.done[t] = 1;
        }
    }

    // ---- wait for schedule ----
    if (tid == 0) {
        volatile int* f = &g_flags.sched_ready;
        while (!*f) __nanosleep(64);
    }
    __syncthreads();
    __threadfence();

    const int ntasks  = g_ntasks;
    const int fdeg255 = g_fdeg[255];

    // ---- dataflow conv tasks ----
    for (int t = bid - 1; t < ntasks; t += nb - 1) {
        const int ni = t >> 6;
        const int pb = t & 63;
        const int n  = g_order[ni];
        const int C  = g_fdeg[n];
        const int* fin = g_fin + n * MAXC;
        const int* fcc = g_fcc + n * MAXC;
        const float* wbase = conv_w + (size_t)n * cmax * 25;

        const int CW = C < 16 ? C : 16;
        for (int i = tid; i < CW * 25; i += 128) {       // weight prefetch (flag-independent)
            int c = i / 25, r = i - c * 25;
            F2U u; float w = wbase[fcc[c] * 25 + r];
            u.f = make_float2(w, w);
            sm.cv.wk2[c * 25 + r] = u.u;
        }
        for (int k = tid; k < C; k += 128) {             // wait for inputs
            volatile int* f = &g_flags.done[fin[k] * 64 + pb];
            while (!*f) __nanosleep(32);
        }
        __threadfence();
        __syncthreads();

        stage_img(sm.cv.img[0], g_act + ((size_t)fin[0] * 128 + pb * 2) * 784, tid);
        __syncthreads();

        ull acc[7];
        { F2U b2; float b = conv_b[n]; b2.f = make_float2(b, b);
#pragma unroll
          for (int o = 0; o < 7; ++o) acc[o] = b2.u; }

        for (int c = 0; c < C; ++c) {
            const int buf = c & 1;
            if (c + 1 < C) {
                stage_img(sm.cv.img[buf ^ 1],
                          g_act + ((size_t)fin[c + 1] * 128 + pb * 2) * 784, tid);
                if (c + 1 >= 16 && tid < 25) {
                    F2U u; float w = wbase[fcc[c + 1] * 25 + tid];
                    u.f = make_float2(w, w);
                    sm.cv.wk2[(16 + ((c + 1) & 1)) * 25 + tid] = u.u;
                }
            }
            if (tid < 112) {
                const ull* w2 = sm.cv.wk2 + ((c < 16) ? c : (16 + (c & 1))) * 25;
                conv_acc2((const ull*)sm.cv.img[buf] + yy * 33 + xx0, w2, acc);
            }
            __syncthreads();
        }
        if (tid < 112) {
            float* d0 = g_act + ((size_t)n * 128 + pb * 2) * 784 + yy * 28 + xx0;
#pragma unroll
            for (int o = 0; o < 7; ++o) {
                F2U u; u.u = acc[o];
                d0[o]       = fmaxf(u.f.x, 0.f);
                d0[784 + o] = fmaxf(u.f.y, 0.f);
            }
        }
        __threadfence();
        __syncthreads();
        if (tid == 0) *(volatile int*)&g_flags.done[n * 64 + pb] = 1;
    }

    // ---- FC1 block tasks: 8 tiles (4 h x 2 b-halves) x KS k-splits ----
    {
        const int Kc = fdeg255 * 49;     // k-chunks of 16 px
        const int* fin = g_fin + 255 * MAXC;
        const int* fcc = g_fcc + 255 * MAXC;
        for (int t = bid - 1; t < 8 * KS; t += nb - 1) {
            const int tile = t / KS;
            const int ks   = t - tile * KS;
            const int h0   = (tile >> 1) * 64;
            const int b0   = (tile & 1) * 64;

            for (int i = tid; i < fdeg255 * 32; i += 128) {   // gate on 32 pbs of this half
                volatile int* f = &g_flags.done[fin[i >> 5] * 64 + (b0 >> 1) + (i & 31)];
                while (!*f) __nanosleep(32);
            }
            __threadfence();
            __syncthreads();

            const int hg = tid >> 4;     // 0..7 -> 8 h each
            const int bg = tid & 15;     // 0..15 -> 4 b each
            ull acc[4][4];
#pragma unroll
            for (int i = 0; i < 4; ++i)
#pragma unroll
                for (int j = 0; j < 4; ++j) acc[i][j] = 0ull;

            for (int kidx = ks; kidx < Kc; kidx += KS) {
                const int c  = kidx / 49;
                const int p0 = (kidx - c * 49) * 16;
                const float* wrow = fc1_w + (size_t)fcc[c] * 784 + p0;
                const float* arow = g_act + ((size_t)fin[c] * 128 + b0) * 784 + p0;
#pragma unroll
                for (int u = 0; u < 2; ++u) {      // stage weights 64h x 16k
                    int q = tid + u * 128;
                    int row = q >> 2, c4 = q & 3;
                    int h = h0 + row;
                    float4 v = (h < 200) ? *(const float4*)(wrow + (size_t)h * fcK + c4 * 4)
                                         : make_float4(0.f, 0.f, 0.f, 0.f);
                    sm.fc.w[c4 * 4 + 0][row] = v.x; sm.fc.w[c4 * 4 + 1][row] = v.y;
                    sm.fc.w[c4 * 4 + 2][row] = v.z; sm.fc.w[c4 * 4 + 3][row] = v.w;
                }
#pragma unroll
                for (int u = 0; u < 2; ++u) {      // stage acts 64b x 16k (dup-packed)
                    int q = tid + u * 128;
                    int row = q >> 2, c4 = q & 3;
                    float4 v = *(const float4*)(arow + (size_t)row * 784 + c4 * 4);
                    sm.fc.a[c4 * 4 + 0][row] = make_float2(v.x, v.x);
                    sm.fc.a[c4 * 4 + 1][row] = make_float2(v.y, v.y);
                    sm.fc.a[c4 * 4 + 2][row] = make_float2(v.z, v.z);
                    sm.fc.a[c4 * 4 + 3][row] = make_float2(v.w, v.w);
                }
                __syncthreads();
#pragma unroll
                for (int k = 0; k < 16; ++k) {
                    const ull* wp  = (const ull*)&sm.fc.w[k][hg * 8];
                    const ull* ap2 = (const ull*)&sm.fc.a[k][bg * 4];
                    ull w0 = wp[0], w1 = wp[1], w2v = wp[2], w3 = wp[3];
                    ull a0 = ap2[0], a1 = ap2[1], a2 = ap2[2], a3 = ap2[3];
                    FMA2(acc[0][0], w0,  a0); FMA2(acc[0][1], w0,  a1);
                    FMA2(acc[0][2], w0,  a2); FMA2(acc[0][3], w0,  a3);
                    FMA2(acc[1][0], w1,  a0); FMA2(acc[1][1], w1,  a1);
                    FMA2(acc[1][2], w1,  a2); FMA2(acc[1][3], w1,  a3);
                    FMA2(acc[2][0], w2v, a0); FMA2(acc[2][1], w2v, a1);
                    FMA2(acc[2][2], w2v, a2); FMA2(acc[2][3], w2v, a3);
                    FMA2(acc[3][0], w3,  a0); FMA2(acc[3][1], w3,  a1);
                    FMA2(acc[3][2], w3,  a2); FMA2(acc[3][3], w3,  a3);
                }
                __syncthreads();
            }
            if (h0 + hg * 8 < 200) {
#pragma unroll
                for (int i = 0; i < 4; ++i)
#pragma unroll
                    for (int j = 0; j < 4; ++j) {
                        F2U u; u.u = acc[i][j];
                        int h = h0 + hg * 8 + i * 2;
                        int b = b0 + bg * 4 + j;
                        atomicAdd(&g_flags.hidden[b * 200 + h],     u.f.x);
                        atomicAdd(&g_flags.hidden[b * 200 + h + 1], u.f.y);
                    }
            }
            __threadfence();
            __syncthreads();
            if (tid == 0) atomicAdd(&g_flags.hcnt[b0 >> 6], 1);
        }
    }

    // ---- FC2 + log_softmax: warp tasks ----
    {
        const int lane = tid & 31;
        const int gw   = (bid - 1) * 4 + (tid >> 5);
        const int strd = (nb - 1) * 4;
        for (int b = gw; b < 128; b += strd) {
            if (lane == 0) {
                volatile int* cc = &g_flags.hcnt[b >> 6];
                while (*cc < 4 * KS) __nanosleep(64);
            }
            __syncwarp();
            __threadfence();
            float acc = 0.f;
            if (lane < 10) {
                acc = fc2_b[lane];
                const float* wp = fc2_w + lane * 200;
                const float* hp = g_flags.hidden + b * 200;
#pragma unroll 5
                for (int h4 = 0; h4 < 50; ++h4) {
                    float4 w  = ((const float4*)wp)[h4];
                    float4 hv = ((const float4*)hp)[h4];
                    float4 fb = ((const float4*)fc1_b)[h4];
                    acc += fmaxf(hv.x + fb.x, 0.f) * w.x + fmaxf(hv.y + fb.y, 0.f) * w.y
                         + fmaxf(hv.z + fb.z, 0.f) * w.z + fmaxf(hv.w + fb.w, 0.f) * w.w;
                }
            }
            float m = (lane < 10) ? acc : -1e30f;
#pragma unroll
            for (int off = 16; off; off >>= 1) m = fmaxf(m, __shfl_xor_sync(0xffffffffu, m, off));
            float e = (lane < 10) ? expf(acc - m) : 0.f;
            float s = e;
#pragma unroll
            for (int off = 16; off; off >>= 1) s += __shfl_xor_sync(0xffffffffu, s, off);
            const float lse = m + logf(s);
            if (lane < 10) out[b * 10 + lane] = acc - lse;
        }
    }
}

// ---------------- launch: ONE memset + ONE kernel ----------------
extern "C" void kernel_launch(void* const* d_in, const int* in_sizes, int n_in,
                              void* d_out, int out_size) {
    const float* x      = (const float*)d_in[0];
    const int*   src    = (const int*)  d_in[1];
    const int*   tgt    = (const int*)  d_in[2];
    const float* conv_w = (const float*)d_in[3];
    const float* conv_b = (const float*)d_in[4];
    const float* fc1_w  = (const float*)d_in[5];
    const float* fc1_b  = (const float*)d_in[6];
    const float* fc2_w  = (const float*)d_in[7];
    const float* fc2_b  = (const float*)d_in[8];

    const int cmax = in_sizes[3] / (NN * 25);
    const int fcK  = in_sizes[5] / 200;

    void* flagsPtr = nullptr;
    cudaGetSymbolAddress(&flagsPtr, g_flags);
    cudaMemsetAsync(flagsPtr, 0, sizeof(Flags), 0);

    int dev = 0, sms = 0, occ = 0;
    cudaGetDevice(&dev);
    cudaDeviceGetAttribute(&sms, cudaDevAttrMultiProcessorCount, dev);
    cudaOccupancyMaxActiveBlocksPerMultiprocessor(&occ, net_kernel, 128, 0);
    int nb = sms * occ;
    if (nb < 130) nb = 130;

    net_kernel<<<nb, 128>>>(x, src, tgt, conv_w, conv_b, fc1_w, fc1_b,
                            fc2_w, fc2_b, (float*)d_out, cmax, fcK, nb);
}